// round 7
// baseline (speedup 1.0000x reference)
#include <cuda_runtime.h>
#include <cuda_bf16.h>
#include <cstdint>

namespace {

constexpr int S = 8192;          // sequence length per batch row
constexpr int T = 32768;         // 4 * 8192 tokens
constexpr int H = 64;            // hash dim (K of GEMM)
constexpr int MOUT = 1024;       // model dim (N of GEMM)
constexpr long long HASH_MULT = 92821;
constexpr long long NUM_BUCKETS = 2000003;

constexpr int BM = 64;           // tokens per block
constexpr int BN = 64;           // output cols per inner iteration
constexpr int NT = MOUT / BN;    // 16 N-tiles
constexpr int AST = H + 8;       // padded smem row stride (72 bf16 = 144 B)
constexpr int STAGES = 4;        // Ws ring depth (prefetch distance 3)

// proj_w pre-converted to bf16 with PERMUTED rows, row-major [MOUT][H].
// Logical output col L lives at row perm(L); within each 16-row group
//   p(L16) = (L16 & 2) * 4 + ((L16 >> 2) & 3) * 2 + (L16 & 1)
// so each MMA lane's 4 accumulators cover 4 CONSECUTIVE logical columns
// and the epilogue uses fully-formed STG.128 stores.
__device__ __nv_bfloat16 g_wbf16[MOUT * H];

__global__ void convert_w_kernel(const float* __restrict__ proj) {
    int base = (blockIdx.x * blockDim.x + threadIdx.x) * 8;
    int row = base >> 6;          // logical output column L
    int col = base & 63;          // position within the H=64 row
    int l16 = row & 15;
    int prow = (row & ~15) + ((l16 & 2) << 2) + (((l16 >> 2) & 3) << 1) + (l16 & 1);

    float4 v0 = *reinterpret_cast<const float4*>(proj + base);
    float4 v1 = *reinterpret_cast<const float4*>(proj + base + 4);
    __nv_bfloat162 b[4];
    b[0] = __floats2bfloat162_rn(v0.x, v0.y);
    b[1] = __floats2bfloat162_rn(v0.z, v0.w);
    b[2] = __floats2bfloat162_rn(v1.x, v1.y);
    b[3] = __floats2bfloat162_rn(v1.z, v1.w);
    *reinterpret_cast<uint4*>(g_wbf16 + prow * H + col) =
        *reinterpret_cast<uint4*>(b);
}

__device__ __forceinline__ void ldmatrix_x4(uint32_t r[4], uint32_t addr) {
    asm volatile(
        "ldmatrix.sync.aligned.m8n8.x4.shared.b16 {%0,%1,%2,%3}, [%4];"
        : "=r"(r[0]), "=r"(r[1]), "=r"(r[2]), "=r"(r[3])
        : "r"(addr));
}

__device__ __forceinline__ void mma_bf16(float c[4], const uint32_t a[4],
                                         uint32_t b0, uint32_t b1) {
    asm volatile(
        "mma.sync.aligned.m16n8k16.row.col.f32.bf16.bf16.f32 "
        "{%0,%1,%2,%3}, {%4,%5,%6,%7}, {%8,%9}, {%0,%1,%2,%3};"
        : "+f"(c[0]), "+f"(c[1]), "+f"(c[2]), "+f"(c[3])
        : "r"(a[0]), "r"(a[1]), "r"(a[2]), "r"(a[3]), "r"(b0), "r"(b1));
}

__device__ __forceinline__ void cp_async16(uint32_t smem, const void* gmem) {
    asm volatile("cp.async.cg.shared.global [%0], [%1], 16;"
                 :: "r"(smem), "l"(gmem));
}
__device__ __forceinline__ void cp_commit() {
    asm volatile("cp.async.commit_group;");
}
template <int N>
__device__ __forceinline__ void cp_wait() {
    asm volatile("cp.async.wait_group %0;" :: "n"(N));
}

__global__ __launch_bounds__(256, 4)
void bigram_kernel(const int* __restrict__ ids, const float* __restrict__ table,
                   float* __restrict__ out) {
    __shared__ __align__(16) __nv_bfloat16 As[BM][AST];          // emb (M x K)
    __shared__ __align__(16) __nv_bfloat16 Ws[STAGES][BN][AST];  // W ring

    const int tid = threadIdx.x;
    const int warp = tid >> 5;
    const int lane = tid & 31;
    const int wm = warp >> 1;   // 0..3 : M position (16 rows each)
    const int wn = warp & 1;    // 0..1 : N position (32 cols each)
    const int t0 = blockIdx.x * BM;

    // ---- Local layout detection ----
    const int probe = ids[2 * (tid & 63) + 1];
    const int id_stride = __syncthreads_or(probe) ? 1 : 2;

    // ---- Kick off W prefetch for tiles 0..2 (independent of gather) ----
    const int j0 = tid;                 // uint4 index 0..255
    const int j1 = tid + 256;           // uint4 index 256..511
    const int r0 = j0 >> 3, c0 = (j0 & 7) * 8;
    const int r1 = j1 >> 3, c1 = (j1 & 7) * 8;
    const uint32_t ws_s0 = (uint32_t)__cvta_generic_to_shared(&Ws[0][r0][c0]);
    const uint32_t ws_s1 = (uint32_t)__cvta_generic_to_shared(&Ws[0][r1][c1]);
    constexpr uint32_t WSZ = BN * AST * 2;  // stage stride in bytes
#pragma unroll
    for (int p = 0; p < STAGES - 1; p++) {
        cp_async16(ws_s0 + p * WSZ, g_wbf16 + (p * BN + r0) * H + c0);
        cp_async16(ws_s1 + p * WSZ, g_wbf16 + (p * BN + r1) * H + c1);
        cp_commit();
    }

    // ---- Hash + gather embedding tile (once per block) ----
    {
        const int tl = tid >> 2;           // local token 0..63
        const int q = tid & 3;             // 16-float quarter of the row
        const int t = t0 + tl;
        long long cur = ids[(long long)t * id_stride];
        long long prev = ((t & (S - 1)) == 0)
                             ? 0
                             : (long long)ids[(long long)(t - 1) * id_stride];
        long long h = (prev * HASH_MULT + cur) % NUM_BUCKETS;
        const float4* src =
            reinterpret_cast<const float4*>(table + h * H + q * 16);
        __nv_bfloat162* dst = reinterpret_cast<__nv_bfloat162*>(&As[tl][q * 16]);
#pragma unroll
        for (int i = 0; i < 4; i++) {
            float4 v = src[i];
            dst[2 * i]     = __floats2bfloat162_rn(v.x, v.y);
            dst[2 * i + 1] = __floats2bfloat162_rn(v.z, v.w);
        }
    }
    __syncthreads();  // As tile complete

    // ---- Load A fragments once; reused across all 16 N-tiles ----
    uint32_t afrag[4][4];  // [k-step][reg]
#pragma unroll
    for (int ks = 0; ks < 4; ks++) {
        const int row = wm * 16 + (lane & 15);
        const int col = ks * 16 + ((lane >> 4) << 3);
        uint32_t addr = (uint32_t)__cvta_generic_to_shared(&As[row][col]);
        ldmatrix_x4(afrag[ks], addr);
    }

    const int b_row = wn * 32 + (lane >> 2);
    const int b_col = (lane & 3) * 2;
    const int row_out = t0 + wm * 16 + (lane >> 2);
    float* out_lane = out + (long long)row_out * MOUT + wn * 32 + (lane & 3) * 4;

    for (int nt = 0; nt < NT; nt++) {
        const int buf = nt & (STAGES - 1);
        // Tile nt is 3 commit-groups back -> wait until <=2 pending.
        cp_wait<2>();
        __syncthreads();  // publish tile nt to all warps; retire readers of buf(nt-1)

        // Prefetch tile nt+3 into the buffer last read at iter nt-1 (WAR-safe:
        // issued after the barrier). Always commit a group to keep the
        // wait_group distance constant (empty groups complete immediately).
        if (nt + STAGES - 1 < NT) {
            const int tn = nt + STAGES - 1;
            const int bn = tn & (STAGES - 1);
            cp_async16(ws_s0 + bn * WSZ, g_wbf16 + (tn * BN + r0) * H + c0);
            cp_async16(ws_s1 + bn * WSZ, g_wbf16 + (tn * BN + r1) * H + c1);
        }
        cp_commit();

        // ---- MMA: warp computes 16 x 32 of this 64-col tile ----
        float c[4][4];
#pragma unroll
        for (int ni = 0; ni < 4; ni++)
#pragma unroll
            for (int r = 0; r < 4; r++) c[ni][r] = 0.0f;

#pragma unroll
        for (int ks = 0; ks < 4; ks++) {
#pragma unroll
            for (int ni = 0; ni < 4; ni++) {
                uint32_t b0 = *reinterpret_cast<const uint32_t*>(
                    &Ws[buf][b_row + ni * 8][ks * 16 + b_col]);
                uint32_t b1 = *reinterpret_cast<const uint32_t*>(
                    &Ws[buf][b_row + ni * 8][ks * 16 + b_col + 8]);
                mma_bf16(c[ni], afrag[ks], b0, b1);
            }
        }

        // ---- Epilogue: 4 fully-coalesced STG.128 per warp ----
#pragma unroll
        for (int h = 0; h < 2; h++) {
            float* p = out_lane + nt * BN + h * 16;
            __stcs(reinterpret_cast<float4*>(p),
                   make_float4(c[2 * h][0], c[2 * h][1],
                               c[2 * h + 1][0], c[2 * h + 1][1]));
            __stcs(reinterpret_cast<float4*>(p + (long long)8 * MOUT),
                   make_float4(c[2 * h][2], c[2 * h][3],
                               c[2 * h + 1][2], c[2 * h + 1][3]));
        }
    }
}

}  // namespace

extern "C" void kernel_launch(void* const* d_in, const int* in_sizes, int n_in,
                              void* d_out, int out_size) {
    const int* ids = nullptr;
    const float* table = nullptr;
    const float* proj = nullptr;
    for (int i = 0; i < n_in; i++) {
        if (in_sizes[i] == T) ids = (const int*)d_in[i];
        else if (in_sizes[i] == (int)(NUM_BUCKETS * H)) table = (const float*)d_in[i];
        else if (in_sizes[i] == MOUT * H) proj = (const float*)d_in[i];
    }

    convert_w_kernel<<<MOUT * H / (256 * 8), 256>>>(proj);
    bigram_kernel<<<T / BM, 256>>>(ids, table, (float*)d_out);
}

// round 8
// speedup vs baseline: 1.7138x; 1.7138x over previous
#include <cuda_runtime.h>
#include <cuda_bf16.h>
#include <cstdint>

namespace {

constexpr int S = 8192;          // sequence length per batch row
constexpr int T = 32768;         // 4 * 8192 tokens
constexpr int H = 64;            // hash dim (K of GEMM)
constexpr int MOUT = 1024;       // model dim (N of GEMM)
constexpr long long HASH_MULT = 92821;
constexpr long long NUM_BUCKETS = 2000003;

constexpr int BM = 64;           // tokens per block
constexpr int BN = 64;           // output cols per tile
constexpr int NT = MOUT / BN;    // 16 N-tiles
constexpr int AST = H + 8;       // padded smem row stride for A

// W pre-converted to bf16 and laid out in MMA-FRAGMENT-MAJOR order:
// element (logical out-col L, k) lives at
//   nt=L>>6, wn=(L>>4)&3, L16=L&15, a=L16>>2, ni=(L16>>1)&1, r=L16&1,
//   n=2a+r, ks=k>>4, kk=k&15, hi=kk>>3, ak=(kk&7)>>1, kr=kk&1
//   idx = ((((nt*4+wn)*4+ks)*32 + 4n+ak)*4 + ni*2+hi)*2 + kr
// so warp (wn) at tile nt loads, per ks, one coalesced 512B block of uint4s
// (lane l -> its exact B-fragment regs {b0_ni0,b1_ni0,b0_ni1,b1_ni1}), and
// lane l's accumulators land on 4 CONSECUTIVE logical columns (STG.128).
__device__ __nv_bfloat16 g_wfrag[MOUT * H];

__global__ void convert_w_kernel(const float* __restrict__ proj) {
    int gid = blockIdx.x * blockDim.x + threadIdx.x;   // 8192 threads
    int L = gid >> 3;            // logical output column 0..1023
    int kb = (gid & 7) * 8;      // k base (8 elements per thread)

    int nt = L >> 6, wn = (L >> 4) & 3, l16 = L & 15;
    int a = l16 >> 2, ni = (l16 >> 1) & 1, r = l16 & 1;
    int n = 2 * a + r;

    float4 v0 = *reinterpret_cast<const float4*>(proj + L * H + kb);
    float4 v1 = *reinterpret_cast<const float4*>(proj + L * H + kb + 4);
    float v[8] = {v0.x, v0.y, v0.z, v0.w, v1.x, v1.y, v1.z, v1.w};

#pragma unroll
    for (int i = 0; i < 8; i++) {
        int k = kb + i;
        int ks = k >> 4, kk = k & 15;
        int hi = kk >> 3, ak = (kk & 7) >> 1, kr = kk & 1;
        int idx = ((((nt * 4 + wn) * 4 + ks) * 32 + 4 * n + ak) * 4 +
                   ni * 2 + hi) * 2 + kr;
        g_wfrag[idx] = __float2bfloat16(v[i]);
    }
}

__device__ __forceinline__ void ldmatrix_x4(uint32_t r[4], uint32_t addr) {
    asm volatile(
        "ldmatrix.sync.aligned.m8n8.x4.shared.b16 {%0,%1,%2,%3}, [%4];"
        : "=r"(r[0]), "=r"(r[1]), "=r"(r[2]), "=r"(r[3])
        : "r"(addr));
}

__device__ __forceinline__ void mma_bf16(float c[4], const uint32_t a[4],
                                         uint32_t b0, uint32_t b1) {
    asm volatile(
        "mma.sync.aligned.m16n8k16.row.col.f32.bf16.bf16.f32 "
        "{%0,%1,%2,%3}, {%4,%5,%6,%7}, {%8,%9}, {%0,%1,%2,%3};"
        : "+f"(c[0]), "+f"(c[1]), "+f"(c[2]), "+f"(c[3])
        : "r"(a[0]), "r"(a[1]), "r"(a[2]), "r"(a[3]), "r"(b0), "r"(b1));
}

__global__ __launch_bounds__(256, 4)
void bigram_kernel(const int* __restrict__ ids, const float* __restrict__ table,
                   float* __restrict__ out) {
    __shared__ __align__(16) __nv_bfloat16 As[BM][AST];   // emb tile only

    const int tid = threadIdx.x;
    const int warp = tid >> 5;
    const int lane = tid & 31;
    const int wm = warp >> 2;   // 0..1 : M position (32 rows each)
    const int wn = warp & 3;    // 0..3 : N position (16 cols per tile)
    const int t0 = blockIdx.x * BM;

    // ---- Local layout detection ----
    const int probe = ids[2 * (tid & 63) + 1];
    const int id_stride = __syncthreads_or(probe) ? 1 : 2;

    // ---- Hash + gather embedding tile (streaming loads: keep L1 for W) ----
    {
        const int tl = tid >> 2;           // local token 0..63
        const int q = tid & 3;             // 16-float quarter of the row
        const int t = t0 + tl;
        long long cur = ids[(long long)t * id_stride];
        long long prev = ((t & (S - 1)) == 0)
                             ? 0
                             : (long long)ids[(long long)(t - 1) * id_stride];
        long long h = (prev * HASH_MULT + cur) % NUM_BUCKETS;
        const float4* src =
            reinterpret_cast<const float4*>(table + h * H + q * 16);
        __nv_bfloat162* dst = reinterpret_cast<__nv_bfloat162*>(&As[tl][q * 16]);
#pragma unroll
        for (int i = 0; i < 4; i++) {
            float4 v = __ldcs(src + i);
            dst[2 * i]     = __floats2bfloat162_rn(v.x, v.y);
            dst[2 * i + 1] = __floats2bfloat162_rn(v.z, v.w);
        }
    }
    __syncthreads();  // the ONLY barrier

    // ---- Load A fragments once; reused across all 16 N-tiles ----
    uint32_t afrag[2][4][4];  // [m-subtile][k-step][reg]
#pragma unroll
    for (int mi = 0; mi < 2; mi++) {
#pragma unroll
        for (int ks = 0; ks < 4; ks++) {
            const int row = wm * 32 + mi * 16 + (lane & 15);
            const int col = ks * 16 + ((lane >> 4) << 3);
            uint32_t addr = (uint32_t)__cvta_generic_to_shared(&As[row][col]);
            ldmatrix_x4(afrag[mi][ks], addr);
        }
    }

    // B fragments: direct from fragment-major global (L1-resident).
    // uint4 index: nt*512 + wn*128 + ks*32 + lane
    const uint4* wf = reinterpret_cast<const uint4*>(g_wfrag) + wn * 128 + lane;
    const int row0 = t0 + wm * 32 + (lane >> 2);
    float* out_lane = out + (long long)row0 * MOUT + wn * 16 + (lane & 3) * 4;

    for (int nt = 0; nt < NT; nt++) {
        float c[2][2][4];
#pragma unroll
        for (int mi = 0; mi < 2; mi++)
#pragma unroll
            for (int ni = 0; ni < 2; ni++)
#pragma unroll
                for (int r = 0; r < 4; r++) c[mi][ni][r] = 0.0f;

        const uint4* wp = wf + nt * 512;
#pragma unroll
        for (int ks = 0; ks < 4; ks++) {
            const uint4 b = wp[ks * 32];   // LDG.128, coalesced, L1-hot
            mma_bf16(c[0][0], afrag[0][ks], b.x, b.y);
            mma_bf16(c[0][1], afrag[0][ks], b.z, b.w);
            mma_bf16(c[1][0], afrag[1][ks], b.x, b.y);
            mma_bf16(c[1][1], afrag[1][ks], b.z, b.w);
        }

        // ---- Epilogue: 4 STG.128 per warp (cols 4a..4a+3 contiguous) ----
#pragma unroll
        for (int mi = 0; mi < 2; mi++) {
            float* p = out_lane + (long long)(mi * 16) * MOUT + nt * BN;
            *reinterpret_cast<float4*>(p) =
                make_float4(c[mi][0][0], c[mi][0][1], c[mi][1][0], c[mi][1][1]);
            *reinterpret_cast<float4*>(p + (long long)8 * MOUT) =
                make_float4(c[mi][0][2], c[mi][0][3], c[mi][1][2], c[mi][1][3]);
        }
    }
}

}  // namespace

extern "C" void kernel_launch(void* const* d_in, const int* in_sizes, int n_in,
                              void* d_out, int out_size) {
    const int* ids = nullptr;
    const float* table = nullptr;
    const float* proj = nullptr;
    for (int i = 0; i < n_in; i++) {
        if (in_sizes[i] == T) ids = (const int*)d_in[i];
        else if (in_sizes[i] == (int)(NUM_BUCKETS * H)) table = (const float*)d_in[i];
        else if (in_sizes[i] == MOUT * H) proj = (const float*)d_in[i];
    }

    convert_w_kernel<<<32, 256>>>(proj);
    bigram_kernel<<<T / BM, 256>>>(ids, table, (float*)d_out);
}